// round 16
// baseline (speedup 1.0000x reference)
#include <cuda_runtime.h>
#include <cuda_fp16.h>
#include <cstdint>

#define B_ 2
#define S_ 2048
#define D_ 1024
#define H_ 16
#define DK_ 64

static const size_t BSD  = (size_t)B_ * S_ * D_;            // 4,194,304
static const size_t BHSS = (size_t)B_ * H_ * S_ * S_;       // 134,217,728

// Device scratch (allocation-free rule)
__device__ __align__(256) __half g_Qh[B_ * H_ * S_ * DK_];  // [z,s,dk]
__device__ __align__(256) __half g_Kh[B_ * H_ * S_ * DK_];
__device__ __align__(256) __half g_Vt[B_ * H_ * DK_ * S_];  // [z,dk,s]
__device__ __align__(256) __half g_Xq16[B_ * S_ * D_];
__device__ __align__(256) __half g_Xk16[B_ * S_ * D_];
__device__ __align__(256) __half g_Xv16[B_ * S_ * D_];
__device__ __align__(256) __half g_Wq16[D_ * D_];
__device__ __align__(256) __half g_Wk16[D_ * D_];
__device__ __align__(256) __half g_Wv16[D_ * D_];
__device__ __align__(256) __half g_Woh[D_ * D_];
__device__ __align__(256) __half g_Wol[D_ * D_];
__device__ __align__(256) __half g_Ctxh[B_ * S_ * D_];
__device__ __align__(256) float  g_Attn[(size_t)B_ * H_ * S_ * S_];
__device__ __align__(256) float  g_OutSpare[B_ * S_ * D_];

// ------------------------- PTX helpers -------------------------
__device__ __forceinline__ void mma16(float* c,
    uint32_t a0, uint32_t a1, uint32_t a2, uint32_t a3,
    uint32_t b0, uint32_t b1)
{
    asm volatile(
        "mma.sync.aligned.m16n8k16.row.col.f32.f16.f16.f32 "
        "{%0,%1,%2,%3}, {%4,%5,%6,%7}, {%8,%9}, {%0,%1,%2,%3};"
        : "+f"(c[0]), "+f"(c[1]), "+f"(c[2]), "+f"(c[3])
        : "r"(a0), "r"(a1), "r"(a2), "r"(a3), "r"(b0), "r"(b1));
}
__device__ __forceinline__ void ldsm4(uint32_t* r, uint32_t addr)
{
    asm volatile("ldmatrix.sync.aligned.m8n8.x4.shared.b16 {%0,%1,%2,%3}, [%4];"
        : "=r"(r[0]), "=r"(r[1]), "=r"(r[2]), "=r"(r[3]) : "r"(addr));
}
__device__ __forceinline__ uint32_t h2u(__half2 h) { return *(uint32_t*)&h; }
__device__ __forceinline__ uint32_t smem_u32_of(const void* p) {
    uint32_t a;
    asm("{ .reg .u64 t; cvta.to.shared.u64 t, %1; cvt.u32.u64 %0, t; }"
        : "=r"(a) : "l"(p));
    return a;
}
__device__ __forceinline__ float ex2f_(float x) {
    float y; asm("ex2.approx.f32 %0, %1;" : "=f"(y) : "f"(x)); return y;
}
__device__ __forceinline__ float lg2f_(float x) {
    float y; asm("lg2.approx.f32 %0, %1;" : "=f"(y) : "f"(x)); return y;
}
#define CP16(dst, src) \
    asm volatile("cp.async.cg.shared.global [%0], [%1], 16;" :: "r"(dst), "l"(src))
#define CP_COMMIT() asm volatile("cp.async.commit_group;" ::: "memory")
#define CP_WAIT1()  asm volatile("cp.async.wait_group 1;" ::: "memory")
#define CP_WAIT0()  asm volatile("cp.async.wait_group 0;" ::: "memory")

// ============================================================================
// One-shot conversion (R11 proven, unchanged).
// ============================================================================
#define XN4 1048576           // BSD/4
#define WN4 262144            // D*D/4
__global__ __launch_bounds__(256) void cvt_all(
    const float* __restrict__ q, const float* __restrict__ k,
    const float* __restrict__ v, const float* __restrict__ Wq,
    const float* __restrict__ Wk, const float* __restrict__ Wv,
    const float* __restrict__ Wo,
    __half* __restrict__ Xq, __half* __restrict__ Xk, __half* __restrict__ Xv,
    __half* __restrict__ W1, __half* __restrict__ W2, __half* __restrict__ W3,
    __half* __restrict__ Wh, __half* __restrict__ Wl)
{
    int i = blockIdx.x * 256 + threadIdx.x;
    if (i >= 3 * XN4 + 3 * WN4) {                    // Wo region: hi/lo split
        int off = i - 3 * XN4 - 3 * WN4;
        if (off >= WN4) return;
        float4 val = *(const float4*)(Wo + (size_t)off * 4);
        __half h0 = __float2half_rn(val.x), h1 = __float2half_rn(val.y);
        __half h2v = __float2half_rn(val.z), h3 = __float2half_rn(val.w);
        *(uint2*)(Wh + (size_t)off * 4) = make_uint2(
            h2u(__halves2half2(h0, h1)), h2u(__halves2half2(h2v, h3)));
        *(uint2*)(Wl + (size_t)off * 4) = make_uint2(
            h2u(__floats2half2_rn(val.x - __half2float(h0), val.y - __half2float(h1))),
            h2u(__floats2half2_rn(val.z - __half2float(h2v), val.w - __half2float(h3))));
        return;
    }
    const float* src; __half* dst; int off;
    if      (i < XN4)             { src = q;  dst = Xq; off = i; }
    else if (i < 2 * XN4)         { src = k;  dst = Xk; off = i - XN4; }
    else if (i < 3 * XN4)         { src = v;  dst = Xv; off = i - 2 * XN4; }
    else if (i < 3 * XN4 + WN4)   { src = Wq; dst = W1; off = i - 3 * XN4; }
    else if (i < 3 * XN4 + 2*WN4) { src = Wk; dst = W2; off = i - 3 * XN4 - WN4; }
    else                          { src = Wv; dst = W3; off = i - 3 * XN4 - 2 * WN4; }
    float4 val = *(const float4*)(src + (size_t)off * 4);
    __half2 a = __floats2half2_rn(val.x, val.y);
    __half2 b = __floats2half2_rn(val.z, val.w);
    *(uint2*)(dst + (size_t)off * 4) = make_uint2(h2u(a), h2u(b));
}

// ============================================================================
// Fused Q/K/V projection — R16: grid.z==3 slice zero-fills the causal tail
// of attn (overlaps store traffic with the compute-bound GEMM slices).
// GEMM slices (z 0..2) byte-identical to R12-R15.
// ============================================================================
#define QSTR 40
#define QMATB 10240
#define QSTGB 20480
__global__ __launch_bounds__(256) void gemmQKV(
    const __half* __restrict__ Xq, const __half* __restrict__ Xk,
    const __half* __restrict__ Xv,
    const __half* __restrict__ W1, const __half* __restrict__ W2,
    const __half* __restrict__ W3,
    const float* __restrict__ bq, const float* __restrict__ bk,
    const float* __restrict__ bv,
    __half* __restrict__ Yq, __half* __restrict__ Yk, __half* __restrict__ Yv2,
    float* __restrict__ attnp, int write_attn)
{
    if (blockIdx.z == 3) {                       // zero-fill slice
        if (!write_attn) return;
        int cid = blockIdx.y * gridDim.x + blockIdx.x;   // 0..255
        #pragma unroll 1
        for (int it = cid * 4; it < cid * 4 + 4; it++) { // 1024 (z,rowblk) items
            int zz = it >> 5, rb = it & 31;
            int cstart = (rb + 1) * 64;
            int ncols = S_ - cstart;
            if (ncols <= 0) continue;
            float* base = attnp + ((size_t)zz * S_ + (size_t)rb * 64) * S_ + cstart;
            for (int r = 0; r < 64; r++) {
                float* rp = base + (size_t)r * S_;
                for (int c = threadIdx.x * 4; c < ncols; c += 1024)
                    *(float4*)(rp + c) = make_float4(0.f, 0.f, 0.f, 0.f);
            }
        }
        return;
    }

    const __half *X16, *W16; const float* bias; __half* Y; int mode;
    if (blockIdx.z == 0)      { X16 = Xq; W16 = W1; bias = bq; Y = Yq;  mode = 1; }
    else if (blockIdx.z == 1) { X16 = Xk; W16 = W2; bias = bk; Y = Yk;  mode = 1; }
    else                      { X16 = Xv; W16 = W3; bias = bv; Y = Yv2; mode = 2; }

    __shared__ __align__(16) __half sbuf[2 * 2 * 128 * QSTR];
    const uint32_t su = smem_u32_of(sbuf);

    const int t = threadIdx.x;
    const int wid = t >> 5, lane = t & 31, g = lane >> 2, tig = lane & 3;
    const int wm = wid & 3, wn = wid >> 2;
    const int bn = blockIdx.x * 128, bm = blockIdx.y * 128;

    const int rowA = (lane & 7) + 8 * ((lane >> 3) & 1);
    const int colA = 8 * (lane >> 4);
    const int rowB = (lane & 7) + 8 * (lane >> 4);
    const int colB = 8 * ((lane >> 3) & 1);
    uint32_t offA[2], offB[4];
    #pragma unroll
    for (int mt = 0; mt < 2; mt++)
        offA[mt] = (uint32_t)(((wm * 32 + mt * 16 + rowA) * QSTR + colA) * 2);
    #pragma unroll
    for (int p = 0; p < 4; p++)
        offB[p] = (uint32_t)(((wn * 64 + p * 16 + rowB) * QSTR + colB) * 2);

    float acc[2][8][4];
    #pragma unroll
    for (int mt = 0; mt < 2; mt++)
        #pragma unroll
        for (int nt = 0; nt < 8; nt++)
            #pragma unroll
            for (int i = 0; i < 4; i++) acc[mt][nt][i] = 0.0f;

    #define QLOAD(stg, k0) do {                                             \
        _Pragma("unroll")                                                   \
        for (int i_ = 0; i_ < 2; i_++) {                                    \
            int c_ = t + i_ * 256;                                          \
            int row_ = c_ >> 2, cc_ = c_ & 3;                               \
            uint32_t d_ = su + (stg) * QSTGB + row_ * 80 + cc_ * 16;        \
            CP16(d_,          X16 + (size_t)(bm + row_) * D_ + (k0) + cc_ * 8); \
            CP16(d_ + QMATB,  W16 + (size_t)(bn + row_) * D_ + (k0) + cc_ * 8); \
        }                                                                   \
    } while (0)

    QLOAD(0, 0); CP_COMMIT();

    const int NK = D_ / 32;
    for (int kt = 0; kt < NK; kt++) {
        if (kt + 1 < NK) { QLOAD((kt + 1) & 1, (kt + 1) * 32); CP_COMMIT(); CP_WAIT1(); }
        else             { CP_WAIT0(); }
        __syncthreads();

        const uint32_t xb = su + (kt & 1) * QSTGB;
        const uint32_t wb = xb + QMATB;

        #pragma unroll
        for (int kk = 0; kk < 32; kk += 16) {
            uint32_t a[2][4];
            ldsm4(a[0], xb + offA[0] + kk * 2);
            ldsm4(a[1], xb + offA[1] + kk * 2);
            #pragma unroll
            for (int p = 0; p < 4; p++) {
                uint32_t b[4];
                ldsm4(b, wb + offB[p] + kk * 2);
                #pragma unroll
                for (int mt = 0; mt < 2; mt++) {
                    mma16(acc[mt][2*p],   a[mt][0], a[mt][1], a[mt][2], a[mt][3], b[0], b[1]);
                    mma16(acc[mt][2*p+1], a[mt][0], a[mt][1], a[mt][2], a[mt][3], b[2], b[3]);
                }
            }
        }
        __syncthreads();
    }

    #pragma unroll
    for (int mt = 0; mt < 2; mt++) {
        int r0 = bm + wm * 32 + mt * 16 + g;
        int r1 = r0 + 8;
        #pragma unroll
        for (int nt = 0; nt < 8; nt++) {
            int col = bn + wn * 64 + nt * 8 + 2 * tig;
            float b0v = __ldg(bias + col), b1v = __ldg(bias + col + 1);
            float* c = acc[mt][nt];
            float v00 = c[0] + b0v, v01 = c[1] + b1v;
            float v10 = c[2] + b0v, v11 = c[3] + b1v;
            int h = col >> 6, d0 = col & 63;
            int bb0 = r0 >> 11, ss0 = r0 & (S_ - 1);
            int bb1 = r1 >> 11, ss1 = r1 & (S_ - 1);
            if (mode == 1) {
                *(__half2*)(Y + (((size_t)bb0 * H_ + h) * S_ + ss0) * DK_ + d0) =
                    __floats2half2_rn(v00, v01);
                *(__half2*)(Y + (((size_t)bb1 * H_ + h) * S_ + ss1) * DK_ + d0) =
                    __floats2half2_rn(v10, v11);
            } else {
                size_t z0 = (size_t)bb0 * H_ + h, z1 = (size_t)bb1 * H_ + h;
                Y[(z0 * DK_ + d0)     * S_ + ss0] = __float2half_rn(v00);
                Y[(z0 * DK_ + d0 + 1) * S_ + ss0] = __float2half_rn(v01);
                Y[(z1 * DK_ + d0)     * S_ + ss1] = __float2half_rn(v10);
                Y[(z1 * DK_ + d0 + 1) * S_ + ss1] = __float2half_rn(v11);
            }
        }
    }
}

// ============================================================================
// Out projection — 2-term split (R15 proven, unchanged).
// ============================================================================
#define T2STGB 30720
__global__ void __launch_bounds__(256, 2) gemm2t(
    const __half* __restrict__ Ch,
    const __half* __restrict__ Wh, const __half* __restrict__ Wl,
    const float* __restrict__ bias, float* __restrict__ Y)
{
    extern __shared__ __half sm3[];
    const uint32_t su = smem_u32_of(sm3);

    const int t = threadIdx.x;
    const int wid = t >> 5, lane = t & 31, g = lane >> 2, tig = lane & 3;
    const int wm = wid & 3, wn = wid >> 2;
    const int bn = blockIdx.x * 128, bm = blockIdx.y * 128;

    const int rowA = (lane & 7) + 8 * ((lane >> 3) & 1);
    const int colA = 8 * (lane >> 4);
    const int rowB = (lane & 7) + 8 * (lane >> 4);
    const int colB = 8 * ((lane >> 3) & 1);
    uint32_t offA[2], offB[4];
    #pragma unroll
    for (int mt = 0; mt < 2; mt++)
        offA[mt] = (uint32_t)(((wm * 32 + mt * 16 + rowA) * QSTR + colA) * 2);
    #pragma unroll
    for (int p = 0; p < 4; p++)
        offB[p] = (uint32_t)(((wn * 64 + p * 16 + rowB) * QSTR + colB) * 2);

    float acc[2][8][4];
    #pragma unroll
    for (int mt = 0; mt < 2; mt++)
        #pragma unroll
        for (int nt = 0; nt < 8; nt++)
            #pragma unroll
            for (int i = 0; i < 4; i++) acc[mt][nt][i] = 0.0f;

    #define T2LOAD(stg, k0) do {                                             \
        _Pragma("unroll")                                                    \
        for (int i_ = 0; i_ < 2; i_++) {                                     \
            int c_ = t + i_ * 256;                                           \
            int row_ = c_ >> 2, cc_ = c_ & 3;                                \
            uint32_t d_ = su + (stg) * T2STGB + row_ * 80 + cc_ * 16;        \
            CP16(d_,             Ch + (size_t)(bm + row_) * D_ + (k0) + cc_ * 8); \
            CP16(d_ + QMATB,     Wh + (size_t)(bn + row_) * D_ + (k0) + cc_ * 8); \
            CP16(d_ + 2 * QMATB, Wl + (size_t)(bn + row_) * D_ + (k0) + cc_ * 8); \
        }                                                                    \
    } while (0)

    T2LOAD(0, 0); CP_COMMIT();

    const int NK = D_ / 32;
    for (int kt = 0; kt < NK; kt++) {
        if (kt + 1 < NK) { T2LOAD((kt + 1) & 1, (kt + 1) * 32); CP_COMMIT(); CP_WAIT1(); }
        else             { CP_WAIT0(); }
        __syncthreads();

        const uint32_t ahb = su + (kt & 1) * T2STGB;
        const uint32_t whb = ahb + QMATB;
        const uint32_t wlb = ahb + 2 * QMATB;

        #pragma unroll
        for (int kk = 0; kk < 32; kk += 16) {
            uint32_t ah[2][4];
            ldsm4(ah[0], ahb + offA[0] + kk * 2);
            ldsm4(ah[1], ahb + offA[1] + kk * 2);
            #pragma unroll
            for (int p = 0; p < 4; p++) {
                uint32_t bh[4], bl[4];
                ldsm4(bh, whb + offB[p] + kk * 2);
                ldsm4(bl, wlb + offB[p] + kk * 2);
                #pragma unroll
                for (int mt = 0; mt < 2; mt++) {
                    mma16(acc[mt][2*p],   ah[mt][0], ah[mt][1], ah[mt][2], ah[mt][3], bh[0], bh[1]);
                    mma16(acc[mt][2*p],   ah[mt][0], ah[mt][1], ah[mt][2], ah[mt][3], bl[0], bl[1]);
                    mma16(acc[mt][2*p+1], ah[mt][0], ah[mt][1], ah[mt][2], ah[mt][3], bh[2], bh[3]);
                    mma16(acc[mt][2*p+1], ah[mt][0], ah[mt][1], ah[mt][2], ah[mt][3], bl[2], bl[3]);
                }
            }
        }
        __syncthreads();
    }

    #pragma unroll
    for (int mt = 0; mt < 2; mt++) {
        int r0 = bm + wm * 32 + mt * 16 + g;
        int r1 = r0 + 8;
        #pragma unroll
        for (int nt = 0; nt < 8; nt++) {
            int col = bn + wn * 64 + nt * 8 + 2 * tig;
            float b0v = __ldg(bias + col), b1v = __ldg(bias + col + 1);
            float* c = acc[mt][nt];
            *(float2*)(Y + (size_t)r0 * D_ + col) = make_float2(c[0] + b0v, c[1] + b1v);
            *(float2*)(Y + (size_t)r1 * D_ + col) = make_float2(c[2] + b0v, c[3] + b1v);
        }
    }
}

// ============================================================================
// Fused flash attention — R16: 128-thread CTAs over 64 q-rows, 6 CTAs/SM.
// Per-warp math/layout identical to R14/R15; no tail zeroing (moved to
// gemmQKV z=3). Arithmetic per row bit-identical (same k-tile order).
// ============================================================================
#define FSTR 72
#define KBYTES (64 * FSTR * 2)
__global__ void __launch_bounds__(128, 6) attn_fused(
    const __half* __restrict__ Qh, const __half* __restrict__ Kh,
    const __half* __restrict__ Vt, float* __restrict__ attn,
    __half* __restrict__ ctxh, int write_attn)
{
    const int qb = (int)gridDim.x - 1 - blockIdx.x;   // long blocks first
    const int q0 = qb * 64;
    const int z = blockIdx.y, bb = z >> 4, hh = z & 15;

    __shared__ __align__(16) __half sK[2][64 * FSTR];
    __shared__ __align__(16) __half sV[2][64 * FSTR];
    const uint32_t suK = smem_u32_of(sK);
    const uint32_t suV = smem_u32_of(sV);

    const int t = threadIdx.x, wid = t >> 5, lane = t & 31;
    const int g = lane >> 2, tig = lane & 3;
    const __half* Q = Qh + (size_t)z * S_ * DK_;
    const __half* K = Kh + (size_t)z * S_ * DK_;
    const __half* V = Vt + (size_t)z * DK_ * S_;
    float* A = attn + (size_t)z * S_ * S_;

    const int r0 = q0 + wid * 16 + g, r1 = r0 + 8;

    const uint32_t ldoff = (uint32_t)((((lane & 7) * FSTR) + (lane >> 3) * 8) * 2);

    uint32_t qa[4][4];
    #pragma unroll
    for (int kk = 0; kk < 4; kk++) {
        qa[kk][0] = *(const uint32_t*)(Q + (size_t)r0 * DK_ + kk * 16 + 2 * tig);
        qa[kk][1] = *(const uint32_t*)(Q + (size_t)r1 * DK_ + kk * 16 + 2 * tig);
        qa[kk][2] = *(const uint32_t*)(Q + (size_t)r0 * DK_ + kk * 16 + 2 * tig + 8);
        qa[kk][3] = *(const uint32_t*)(Q + (size_t)r1 * DK_ + kk * 16 + 2 * tig + 8);
    }

    const int ntl = qb + 1;
    const float c2 = 0.125f * 1.4426950408889634f;   // sc * log2(e)
    float l0 = 0.0f, l1 = 0.0f;

    // loaders: 128 threads, 4 chunks each (tile = 64 rows x 8 x 16B)
    #define LOADK(stg, kb) do {                                        \
        _Pragma("unroll")                                              \
        for (int i_ = 0; i_ < 4; i_++) {                               \
            int c_ = t + i_ * 128;                                     \
            int row_ = c_ >> 3, cc_ = c_ & 7;                          \
            CP16(suK + (stg) * KBYTES + row_ * 144 + cc_ * 16,         \
                 K + (size_t)((kb) + row_) * DK_ + cc_ * 8);           \
        }                                                              \
    } while (0)
    #define LOADV(stg, kb) do {                                        \
        _Pragma("unroll")                                              \
        for (int i_ = 0; i_ < 4; i_++) {                               \
            int c_ = t + i_ * 128;                                     \
            int row_ = c_ >> 3, cc_ = c_ & 7;                          \
            CP16(suV + (stg) * KBYTES + row_ * 144 + cc_ * 16,         \
                 V + (size_t)row_ * S_ + (kb) + cc_ * 8);              \
        }                                                              \
    } while (0)

    // ---------------- Pass A: l = sum exp2(s*c2) ----------------
    LOADK(0, 0); CP_COMMIT();
    for (int kt = 0; kt < ntl; kt++) {
        const int k0 = kt * 64;
        if (kt + 1 < ntl) { LOADK((kt + 1) & 1, (kt + 1) * 64); CP_COMMIT(); CP_WAIT1(); }
        else              { CP_WAIT0(); }
        __syncthreads();

        const uint32_t kbase = suK + (kt & 1) * KBYTES + ldoff;
        const bool edge = (k0 + 63 > q0 + wid * 16);
        #pragma unroll
        for (int nt = 0; nt < 8; nt++) {
            uint32_t kb[8];
            uint32_t a0 = kbase + (uint32_t)(nt * 8 * FSTR * 2);
            ldsm4(kb,     a0);
            ldsm4(kb + 4, a0 + 64);
            float s4[4] = {0.f, 0.f, 0.f, 0.f};
            #pragma unroll
            for (int kk = 0; kk < 4; kk++)
                mma16(s4, qa[kk][0], qa[kk][1], qa[kk][2], qa[kk][3],
                      kb[2 * kk], kb[2 * kk + 1]);
            int kc = k0 + nt * 8 + 2 * tig;
            float e0 = ex2f_(s4[0] * c2);
            float e1 = ex2f_(s4[1] * c2);
            float e2 = ex2f_(s4[2] * c2);
            float e3 = ex2f_(s4[3] * c2);
            if (edge) {
                if (kc     > r0) e0 = 0.0f;
                if (kc + 1 > r0) e1 = 0.0f;
                if (kc     > r1) e2 = 0.0f;
                if (kc + 1 > r1) e3 = 0.0f;
            }
            l0 += e0 + e1;
            l1 += e2 + e3;
        }
        __syncthreads();
    }
    l0 += __shfl_xor_sync(0xffffffffu, l0, 1);
    l0 += __shfl_xor_sync(0xffffffffu, l0, 2);
    l1 += __shfl_xor_sync(0xffffffffu, l1, 1);
    l1 += __shfl_xor_sync(0xffffffffu, l1, 2);
    const float li0 = -lg2f_(l0), li1 = -lg2f_(l1);  // p = ex2(s*c2 + li)

    // ---------------- Pass B: recompute, write p, PV ----------------
    float pv[8][4];
    #pragma unroll
    for (int dt = 0; dt < 8; dt++)
        #pragma unroll
        for (int e = 0; e < 4; e++) pv[dt][e] = 0.0f;

    LOADK(0, 0); LOADV(0, 0); CP_COMMIT();
    for (int kt = 0; kt < ntl; kt++) {
        const int k0 = kt * 64;
        if (kt + 1 < ntl) {
            LOADK((kt + 1) & 1, (kt + 1) * 64);
            LOADV((kt + 1) & 1, (kt + 1) * 64);
            CP_COMMIT(); CP_WAIT1();
        } else {
            CP_WAIT0();
        }
        __syncthreads();

        const uint32_t kbase = suK + (kt & 1) * KBYTES + ldoff;
        const uint32_t vbase = suV + (kt & 1) * KBYTES + ldoff;
        const bool edge = (k0 + 63 > q0 + wid * 16);

        uint32_t pa[4][4];
        #pragma unroll
        for (int nt = 0; nt < 8; nt++) {
            uint32_t kb[8];
            uint32_t a0 = kbase + (uint32_t)(nt * 8 * FSTR * 2);
            ldsm4(kb,     a0);
            ldsm4(kb + 4, a0 + 64);
            float s4[4] = {0.f, 0.f, 0.f, 0.f};
            #pragma unroll
            for (int kk = 0; kk < 4; kk++)
                mma16(s4, qa[kk][0], qa[kk][1], qa[kk][2], qa[kk][3],
                      kb[2 * kk], kb[2 * kk + 1]);
            int kc = k0 + nt * 8 + 2 * tig;
            float p0 = ex2f_(fmaf(s4[0], c2, li0));
            float p1 = ex2f_(fmaf(s4[1], c2, li0));
            float p2 = ex2f_(fmaf(s4[2], c2, li1));
            float p3 = ex2f_(fmaf(s4[3], c2, li1));
            if (edge) {
                if (kc     > r0) p0 = 0.0f;
                if (kc + 1 > r0) p1 = 0.0f;
                if (kc     > r1) p2 = 0.0f;
                if (kc + 1 > r1) p3 = 0.0f;
            }
            if (write_attn) {
                *(float2*)(A + (size_t)r0 * S_ + kc) = make_float2(p0, p1);
                *(float2*)(A + (size_t)r1 * S_ + kc) = make_float2(p2, p3);
            }
            uint32_t h01 = h2u(__floats2half2_rn(p0, p1));
            uint32_t h23 = h2u(__floats2half2_rn(p2, p3));
            int ks = nt >> 1;
            if ((nt & 1) == 0) { pa[ks][0] = h01; pa[ks][1] = h23; }
            else               { pa[ks][2] = h01; pa[ks][3] = h23; }
        }
        #pragma unroll
        for (int dt = 0; dt < 8; dt++) {
            uint32_t vb[8];
            uint32_t a0 = vbase + (uint32_t)(dt * 8 * FSTR * 2);
            ldsm4(vb,     a0);
            ldsm4(vb + 4, a0 + 64);
            #pragma unroll
            for (int kk = 0; kk < 4; kk++)
                mma16(pv[dt], pa[kk][0], pa[kk][1], pa[kk][2], pa[kk][3],
                      vb[2 * kk], vb[2 * kk + 1]);
        }
        __syncthreads();
    }

    // ctx epilogue: fp16 hi only
    #pragma unroll
    for (int dt = 0; dt < 8; dt++) {
        int col = dt * 8 + 2 * tig;
        size_t o0 = ((size_t)bb * S_ + r0) * D_ + hh * DK_ + col;
        size_t o1 = ((size_t)bb * S_ + r1) * D_ + hh * DK_ + col;
        *(__half2*)(ctxh + o0) = __floats2half2_rn(pv[dt][0], pv[dt][1]);
        *(__half2*)(ctxh + o1) = __floats2half2_rn(pv[dt][2], pv[dt][3]);
    }
}

// ============================================================================
extern "C" void kernel_launch(void* const* d_in, const int* in_sizes, int n_in,
                              void* d_out, int out_size)
{
    const float* q  = (const float*)d_in[0];
    const float* k  = (const float*)d_in[1];
    const float* v  = (const float*)d_in[2];
    const float* Wq = (const float*)d_in[5];
    const float* bq = (const float*)d_in[6];
    const float* Wk = (const float*)d_in[7];
    const float* bk = (const float*)d_in[8];
    const float* Wv = (const float*)d_in[9];
    const float* bv = (const float*)d_in[10];
    const float* Wo = (const float*)d_in[11];
    const float* bo = (const float*)d_in[12];

    __half *gQh, *gKh, *gVt, *gXq, *gXk, *gXv, *gW1, *gW2, *gW3, *gWoh, *gWol,
           *gCtxh;
    float *gAttn, *gOutSpare;
    cudaGetSymbolAddress((void**)&gQh,   g_Qh);
    cudaGetSymbolAddress((void**)&gKh,   g_Kh);
    cudaGetSymbolAddress((void**)&gVt,   g_Vt);
    cudaGetSymbolAddress((void**)&gXq,   g_Xq16);
    cudaGetSymbolAddress((void**)&gXk,   g_Xk16);
    cudaGetSymbolAddress((void**)&gXv,   g_Xv16);
    cudaGetSymbolAddress((void**)&gW1,   g_Wq16);
    cudaGetSymbolAddress((void**)&gW2,   g_Wk16);
    cudaGetSymbolAddress((void**)&gW3,   g_Wv16);
    cudaGetSymbolAddress((void**)&gWoh,  g_Woh);
    cudaGetSymbolAddress((void**)&gWol,  g_Wol);
    cudaGetSymbolAddress((void**)&gCtxh, g_Ctxh);
    cudaGetSymbolAddress((void**)&gAttn, g_Attn);
    cudaGetSymbolAddress((void**)&gOutSpare, g_OutSpare);

    float* outp = (float*)d_out;
    float* attn = gAttn;
    int write_attn = 0;
    if ((size_t)out_size == BSD + BHSS) {
        outp = (float*)d_out;
        attn = (float*)d_out + BSD;
        write_attn = 1;
    } else if ((size_t)out_size == BHSS) {
        attn = (float*)d_out;
        outp = gOutSpare;
        write_attn = 1;
    }

    static int smem_set = 0;
    if (!smem_set) {
        cudaFuncSetAttribute(gemm2t, cudaFuncAttributeMaxDynamicSharedMemorySize,
                             2 * T2STGB);
        smem_set = 1;
    }

    const dim3 blk(256);
    const int CVT_N = 3 * XN4 + 4 * WN4;             // includes Wo hi/lo region

    cvt_all<<<(CVT_N + 255) / 256, blk>>>(q, k, v, Wq, Wk, Wv, Wo,
                                          gXq, gXk, gXv, gW1, gW2, gW3,
                                          gWoh, gWol);

    gemmQKV<<<dim3(D_ / 128, (B_ * S_) / 128, 4), blk>>>(
        gXq, gXk, gXv, gW1, gW2, gW3, bq, bk, bv, gQh, gKh, gVt,
        attn, write_attn);

    attn_fused<<<dim3(S_ / 64, B_ * H_), dim3(128)>>>(gQh, gKh, gVt, attn,
                                                      gCtxh, write_attn);

    gemm2t<<<dim3(D_ / 128, (B_ * S_) / 128), blk, 2 * T2STGB>>>(
        gCtxh, gWoh, gWol, bo, outp);
}